// round 2
// baseline (speedup 1.0000x reference)
#include <cuda_runtime.h>
#include <cuda_bf16.h>
#include <math.h>

// Problem constants (fixed by setup_inputs)
#define NF   1024      // features (rows of A)
#define NN   2048      // nodes (cols of A)
#define DIM  64
#define K12  768       // 12*dim
#define NFEAT 256      // 4*dim
#define EPS_F 1e-6f
#define LN_EPS_F 1e-5f

// Device scratch (no allocations allowed)
__device__ unsigned int g_mask[NN * 32];        // 256 KB: bitmask per node over features
__device__ float        g_feat[NN * NFEAT];     // 2 MB:  [mean | min | max | std]
__device__ float        g_logdeg[NN];
__device__ float        g_meanscale[256];
__device__ float        g_Wt[K12 * DIM];        // W transposed to (768, 64) k-major

// ---------------------------------------------------------------------------
// K0: transpose W (64,768) -> Wt (768,64)
// ---------------------------------------------------------------------------
__global__ void k0_transW(const float* __restrict__ W) {
    int idx = blockIdx.x * 256 + threadIdx.x;
    if (idx < K12 * DIM) {
        int d = idx / K12;
        int k = idx % K12;
        g_Wt[k * DIM + d] = W[idx];   // coalesced read of W, scattered write (tiny)
    }
}

// ---------------------------------------------------------------------------
// K1: build adjacency bitmasks. Block = 256 nodes x 1 word (32 features).
// Reads A coalesced along n (128B per warp per row).
// ---------------------------------------------------------------------------
__global__ void k1_mask(const float* __restrict__ A) {
    int n = blockIdx.x * 256 + threadIdx.x;   // node
    int w = blockIdx.y;                       // feature word
    unsigned m = 0;
#pragma unroll
    for (int r = 0; r < 32; r++) {
        float a = A[(w * 32 + r) * NN + n];
        if (a != 0.0f) m |= (1u << r);
    }
    g_mask[n * 32 + w] = m;
}

// ---------------------------------------------------------------------------
// K2: per-node stats. Block = 1 node, 64 threads (one per dim).
// Build compact edge list in shared (order-free via shared atomics),
// then unroll-4 gather of x rows for MLP.
// ---------------------------------------------------------------------------
__global__ void k2_stats(const float* __restrict__ x) {
    int n = blockIdx.x;
    int d = threadIdx.x;  // 0..63

    __shared__ unsigned sMask[32];
    __shared__ unsigned short sList[1024];
    __shared__ int sCnt;

    if (d == 0) sCnt = 0;
    if (d < 32) sMask[d] = g_mask[n * 32 + d];
    __syncthreads();

    if (d < 32) {
        unsigned m = sMask[d];
        int base = d * 32;
        while (m) {
            int b = __ffs(m) - 1;
            m &= m - 1;
            int pos = atomicAdd(&sCnt, 1);
            sList[pos] = (unsigned short)(base + b);
        }
    }
    __syncthreads();

    int cnt = sCnt;
    float s = 0.0f, sq = 0.0f;
    float mn = INFINITY, mx = -INFINITY;

    int j = 0;
    for (; j + 4 <= cnt; j += 4) {
        int f0 = sList[j], f1 = sList[j + 1], f2 = sList[j + 2], f3 = sList[j + 3];
        float x0 = x[f0 * DIM + d];
        float x1 = x[f1 * DIM + d];
        float x2 = x[f2 * DIM + d];
        float x3 = x[f3 * DIM + d];
        s  += (x0 + x1) + (x2 + x3);
        sq += (x0 * x0 + x1 * x1) + (x2 * x2 + x3 * x3);
        mn = fminf(mn, fminf(fminf(x0, x1), fminf(x2, x3)));
        mx = fmaxf(mx, fmaxf(fmaxf(x0, x1), fmaxf(x2, x3)));
    }
    for (; j < cnt; j++) {
        int f = sList[j];
        float xv = x[f * DIM + d];
        s += xv; sq += xv * xv;
        mn = fminf(mn, xv); mx = fmaxf(mx, xv);
    }

    float deg  = (float)cnt + 1.0f;           // degree = A.sum(0) + 1
    float mean = s / deg;
    float var  = sq / deg - mean * mean;
    float sd   = sqrtf(fmaxf(var, EPS_F));

    g_feat[n * NFEAT +            d] = mean;
    g_feat[n * NFEAT +  DIM     + d] = mn;
    g_feat[n * NFEAT + 2 * DIM  + d] = mx;
    g_feat[n * NFEAT + 3 * DIM  + d] = sd;
    if (d == 0) g_logdeg[n] = logf(deg);
}

// ---------------------------------------------------------------------------
// K3: per-batch mean of log(deg). One block, shared atomics. Unused batch
// slots produce 0 (never indexed), so batch_size input is not needed.
// ---------------------------------------------------------------------------
__global__ void k3_batch(const int* __restrict__ b_n) {
    __shared__ float ssum[256];
    __shared__ float scnt[256];
    int t = threadIdx.x;
    ssum[t] = 0.0f;
    scnt[t] = 0.0f;
    __syncthreads();
    for (int n = t; n < NN; n += 256) {
        int b = b_n[n];
        atomicAdd(&ssum[b], g_logdeg[n]);
        atomicAdd(&scnt[b], 1.0f);
    }
    __syncthreads();
    g_meanscale[t] = ssum[t] / fmaxf(scnt[t], EPS_F);
}

// ---------------------------------------------------------------------------
// K4: fused (feat x scales) expansion GEMM + bias + LayerNorm + ReLU.
// Block = 16 nodes, 256 threads. Thread t: d = t&63, handles 4 nodes.
// h[n,d] = sum_i feat[n,i]*(W0[i,d] + sc*W1[i,d] + inv*W2[i,d])
// where Wj[i,d] = Wt[(3i+j)*64 + d].
// ---------------------------------------------------------------------------
#define NPB 16           // nodes per block
#define ICH 32           // i (feature) chunk -> 96 Wt rows staged (24 KB)

__global__ void __launch_bounds__(256, 2)
k4_gemm_ln(const float* __restrict__ bias,
           const float* __restrict__ gamma,
           const float* __restrict__ beta,
           const int*   __restrict__ b_n,
           float* __restrict__ out) {
    __shared__ float featS[NPB * NFEAT];      // 16 KB
    __shared__ float wS[3 * ICH * DIM];       // 24 KB
    __shared__ float scS[NPB * 2];
    __shared__ float redS[NPB][2][2];         // node x warp-half x {sum, sumsq}

    int t  = threadIdx.x;
    int nb = blockIdx.x * NPB;

    for (int k = t; k < NPB * NFEAT; k += 256)
        featS[k] = g_feat[nb * NFEAT + k];

    if (t < NPB) {
        int n = nb + t;
        float ms = g_meanscale[b_n[n]];
        float sc = g_logdeg[n] / fmaxf(ms, EPS_F);
        scS[t * 2]     = sc;
        scS[t * 2 + 1] = 1.0f / fmaxf(sc, EPS_F);
    }
    __syncthreads();

    int d = t & 63;
    int g = t >> 6;          // node group 0..3 (4 nodes each)

    float acc[4] = {0.f, 0.f, 0.f, 0.f};
    float sA[4], sB[4];
#pragma unroll
    for (int q = 0; q < 4; q++) {
        sA[q] = scS[(g * 4 + q) * 2];
        sB[q] = scS[(g * 4 + q) * 2 + 1];
    }

    for (int c = 0; c < NFEAT / ICH; c++) {
        __syncthreads();
        for (int k = t; k < 3 * ICH * DIM; k += 256)
            wS[k] = g_Wt[c * (3 * ICH * DIM) + k];
        __syncthreads();

#pragma unroll 4
        for (int il = 0; il < ICH; il++) {
            float w0 = wS[(3 * il    ) * DIM + d];
            float w1 = wS[(3 * il + 1) * DIM + d];
            float w2 = wS[(3 * il + 2) * DIM + d];
            int i = c * ICH + il;
#pragma unroll
            for (int q = 0; q < 4; q++) {
                float fv = featS[(g * 4 + q) * NFEAT + i];
                acc[q] = fmaf(fv,          w0, acc[q]);
                acc[q] = fmaf(fv * sA[q],  w1, acc[q]);
                acc[q] = fmaf(fv * sB[q],  w2, acc[q]);
            }
        }
    }

    // bias + LayerNorm + ReLU
    float bv = bias[d];
    float gv = gamma[d];
    float bt = beta[d];
    int wg = (t >> 5) & 1;   // which warp-half of the 64-thread node group

    float h[4];
#pragma unroll
    for (int q = 0; q < 4; q++) {
        h[q] = acc[q] + bv;
        float s1 = h[q];
        float s2 = h[q] * h[q];
#pragma unroll
        for (int off = 16; off > 0; off >>= 1) {
            s1 += __shfl_xor_sync(0xffffffffu, s1, off);
            s2 += __shfl_xor_sync(0xffffffffu, s2, off);
        }
        if ((t & 31) == 0) {
            int nl = g * 4 + q;
            redS[nl][wg][0] = s1;
            redS[nl][wg][1] = s2;
        }
    }
    __syncthreads();

#pragma unroll
    for (int q = 0; q < 4; q++) {
        int nl = g * 4 + q;
        float tot  = redS[nl][0][0] + redS[nl][1][0];
        float tot2 = redS[nl][0][1] + redS[nl][1][1];
        float mu  = tot * (1.0f / DIM);
        float var = tot2 * (1.0f / DIM) - mu * mu;
        float o = (h[q] - mu) * rsqrtf(var + LN_EPS_F) * gv + bt;
        out[(nb + nl) * DIM + d] = fmaxf(o, 0.0f);
    }
}

// ---------------------------------------------------------------------------
extern "C" void kernel_launch(void* const* d_in, const int* in_sizes, int n_in,
                              void* d_out, int out_size) {
    const float* A     = (const float*)d_in[0];   // (1024, 2048)
    const float* x     = (const float*)d_in[1];   // (1024, 64)
    const float* W     = (const float*)d_in[2];   // (64, 768)
    const float* bias  = (const float*)d_in[3];   // (64)
    const float* gamma = (const float*)d_in[4];   // (64)
    const float* beta  = (const float*)d_in[5];   // (64)
    const int*   b_n   = (const int*)d_in[6];     // (2048)
    float* out = (float*)d_out;                   // (2048, 64)

    k0_transW<<<(K12 * DIM + 255) / 256, 256>>>(W);
    k1_mask<<<dim3(NN / 256, 32), 256>>>(A);
    k2_stats<<<NN, 64>>>(x);
    k3_batch<<<1, 256>>>(b_n);
    k4_gemm_ln<<<NN / NPB, 256>>>(bias, gamma, beta, b_n, out);
}

// round 3
// speedup vs baseline: 1.1720x; 1.1720x over previous
#include <cuda_runtime.h>
#include <cuda_bf16.h>
#include <math.h>

// Problem constants (fixed by setup_inputs)
#define NF   1024      // features (rows of A)
#define NN   2048      // nodes (cols of A)
#define DIM  64
#define K12  768       // 12*dim
#define NFEAT 256      // 4*dim
#define EPS_F 1e-6f
#define LN_EPS_F 1e-5f

// Device scratch (no allocations allowed)
__device__ unsigned int g_mask[NN * 32];        // 256 KB: bitmask per node over features
__device__ float        g_feat[NN * NFEAT];     // 2 MB:  [mean | min | max | std]
__device__ float        g_logdeg[NN];
__device__ float        g_bsum[32];             // per-batch sum of log(deg)
__device__ float        g_bcnt[32];             // per-batch node count
__device__ float        g_Wt[K12 * DIM];        // W transposed to (768, 64) k-major

// ---------------------------------------------------------------------------
// K0 (prep): role-split blocks.
//   blocks [0,192):    transpose W (64,768) -> Wt (768,64); block 0 also zeros
//                      the batch accumulators.
//   blocks [192,448):  build adjacency bitmasks, reading A coalesced along n.
// ---------------------------------------------------------------------------
__global__ void k_prep(const float* __restrict__ W, const float* __restrict__ A) {
    int blk = blockIdx.x;
    int t = threadIdx.x;
    if (blk < 192) {
        int idx = blk * 256 + t;
        if (idx < 32) { g_bsum[idx] = 0.0f; g_bcnt[idx] = 0.0f; }
        // K12*DIM = 49152 = 192*256 exactly
        int d = idx / K12;
        int k = idx % K12;
        g_Wt[k * DIM + d] = W[idx];     // coalesced read, scattered (tiny) write
    } else {
        int bb = blk - 192;             // 0..255
        int n = (bb & 7) * 256 + t;     // node
        int w = bb >> 3;                // feature word 0..31
        unsigned m = 0;
#pragma unroll
        for (int r = 0; r < 32; r++) {
            if (A[(w * 32 + r) * NN + n] != 0.0f) m |= (1u << r);
        }
        g_mask[n * 32 + w] = m;
    }
}

// ---------------------------------------------------------------------------
// K2: per-node stats + batch log-deg accumulation (replaces old k3).
// Block = 4 nodes x 64 threads. Build compact edge lists in shared, then
// unroll-4 gather of x rows for MLP.
// ---------------------------------------------------------------------------
__global__ void k2_stats(const float* __restrict__ x, const int* __restrict__ b_n) {
    int sub = threadIdx.x >> 6;   // node-within-block 0..3
    int d   = threadIdx.x & 63;   // dim lane
    int n   = blockIdx.x * 4 + sub;

    __shared__ unsigned short sList[4][1024];
    __shared__ int sCnt[4];

    if (d == 0) sCnt[sub] = 0;
    __syncthreads();

    if (d < 32) {
        unsigned m = g_mask[n * 32 + d];
        int base = d * 32;
        while (m) {
            int b = __ffs(m) - 1;
            m &= m - 1;
            int pos = atomicAdd(&sCnt[sub], 1);
            sList[sub][pos] = (unsigned short)(base + b);
        }
    }
    __syncthreads();

    int cnt = sCnt[sub];
    float s = 0.0f, sq = 0.0f;
    float mn = INFINITY, mx = -INFINITY;

    int j = 0;
    for (; j + 4 <= cnt; j += 4) {
        int f0 = sList[sub][j], f1 = sList[sub][j + 1];
        int f2 = sList[sub][j + 2], f3 = sList[sub][j + 3];
        float x0 = x[f0 * DIM + d];
        float x1 = x[f1 * DIM + d];
        float x2 = x[f2 * DIM + d];
        float x3 = x[f3 * DIM + d];
        s  += (x0 + x1) + (x2 + x3);
        sq += (x0 * x0 + x1 * x1) + (x2 * x2 + x3 * x3);
        mn = fminf(mn, fminf(fminf(x0, x1), fminf(x2, x3)));
        mx = fmaxf(mx, fmaxf(fmaxf(x0, x1), fmaxf(x2, x3)));
    }
    for (; j < cnt; j++) {
        int f = sList[sub][j];
        float xv = x[f * DIM + d];
        s += xv; sq += xv * xv;
        mn = fminf(mn, xv); mx = fmaxf(mx, xv);
    }

    float deg  = (float)cnt + 1.0f;           // degree = A.sum(0) + 1
    float mean = s / deg;
    float var  = sq / deg - mean * mean;
    float sd   = sqrtf(fmaxf(var, EPS_F));

    g_feat[n * NFEAT +            d] = mean;
    g_feat[n * NFEAT +  DIM     + d] = mn;
    g_feat[n * NFEAT + 2 * DIM  + d] = mx;
    g_feat[n * NFEAT + 3 * DIM  + d] = sd;
    if (d == 0) {
        float ld = logf(deg);
        g_logdeg[n] = ld;
        int b = b_n[n];
        atomicAdd(&g_bsum[b], ld);
        atomicAdd(&g_bcnt[b], 1.0f);
    }
}

// ---------------------------------------------------------------------------
// K4: fused (feat x scales) expansion GEMM + bias + LayerNorm + ReLU.
// Block = 16 nodes, 256 threads. Thread t: d = t&63, handles 4 nodes.
// Features are PRESCALED into shared as float4 (fv, fv*sc, fv*inv, 0) so the
// inner loop is exactly 3 FFMA per (node, i) -- the fp32 fma-pipe floor.
// Dynamic smem: featS4 (64 KB) + wS (24 KB).
// ---------------------------------------------------------------------------
#define NPB 16           // nodes per block
#define ICH 32           // i (feature) chunk -> 96 Wt rows staged (24 KB)
#define K4_SMEM ((NPB * NFEAT * 4 + 3 * ICH * DIM) * 4)

__global__ void __launch_bounds__(256, 1)
k4_gemm_ln(const float* __restrict__ bias,
           const float* __restrict__ gamma,
           const float* __restrict__ beta,
           const int*   __restrict__ b_n,
           float* __restrict__ out) {
    extern __shared__ float smemBuf[];
    float* featS4 = smemBuf;                       // NPB*NFEAT*4 floats (64 KB)
    float* wS     = smemBuf + NPB * NFEAT * 4;     // 3*ICH*DIM floats (24 KB)

    __shared__ float scS[NPB * 2];
    __shared__ float redS[NPB][2][2];              // node x warp-half x {sum, sumsq}

    int t  = threadIdx.x;
    int nb = blockIdx.x * NPB;

    if (t < NPB) {
        int n = nb + t;
        int b = b_n[n];
        float ms = g_bsum[b] / fmaxf(g_bcnt[b], EPS_F);
        float sc = g_logdeg[n] / fmaxf(ms, EPS_F);
        scS[t * 2]     = sc;
        scS[t * 2 + 1] = 1.0f / fmaxf(sc, EPS_F);
    }
    __syncthreads();

    // Prescale features into shared: float4 per (node, i)
    for (int k = t; k < NPB * NFEAT; k += 256) {
        int nl = k >> 8;                            // k / NFEAT
        float fv  = g_feat[nb * NFEAT + k];
        float sc  = scS[nl * 2];
        float inv = scS[nl * 2 + 1];
        reinterpret_cast<float4*>(featS4)[k] = make_float4(fv, fv * sc, fv * inv, 0.0f);
    }

    int d = t & 63;
    int g = t >> 6;          // node group 0..3 (4 nodes each)

    float acc[4] = {0.f, 0.f, 0.f, 0.f};

    for (int c = 0; c < NFEAT / ICH; c++) {
        __syncthreads();
        for (int k = t; k < 3 * ICH * DIM; k += 256)
            wS[k] = g_Wt[c * (3 * ICH * DIM) + k];
        __syncthreads();

#pragma unroll 4
        for (int il = 0; il < ICH; il++) {
            float w0 = wS[(3 * il    ) * DIM + d];
            float w1 = wS[(3 * il + 1) * DIM + d];
            float w2 = wS[(3 * il + 2) * DIM + d];
            int i = c * ICH + il;
#pragma unroll
            for (int q = 0; q < 4; q++) {
                float4 f = reinterpret_cast<const float4*>(featS4)[(g * 4 + q) * NFEAT + i];
                acc[q] = fmaf(f.x, w0, fmaf(f.y, w1, fmaf(f.z, w2, acc[q])));
            }
        }
    }

    // bias + LayerNorm + ReLU
    float bv = bias[d];
    float gv = gamma[d];
    float bt = beta[d];
    int wg = (t >> 5) & 1;   // which warp-half of the 64-thread node group

    float h[4];
#pragma unroll
    for (int q = 0; q < 4; q++) {
        h[q] = acc[q] + bv;
        float s1 = h[q];
        float s2 = h[q] * h[q];
#pragma unroll
        for (int off = 16; off > 0; off >>= 1) {
            s1 += __shfl_xor_sync(0xffffffffu, s1, off);
            s2 += __shfl_xor_sync(0xffffffffu, s2, off);
        }
        if ((t & 31) == 0) {
            int nl = g * 4 + q;
            redS[nl][wg][0] = s1;
            redS[nl][wg][1] = s2;
        }
    }
    __syncthreads();

#pragma unroll
    for (int q = 0; q < 4; q++) {
        int nl = g * 4 + q;
        float tot  = redS[nl][0][0] + redS[nl][1][0];
        float tot2 = redS[nl][0][1] + redS[nl][1][1];
        float mu  = tot * (1.0f / DIM);
        float var = tot2 * (1.0f / DIM) - mu * mu;
        float o = (h[q] - mu) * rsqrtf(var + LN_EPS_F) * gv + bt;
        out[(nb + nl) * DIM + d] = fmaxf(o, 0.0f);
    }
}

// ---------------------------------------------------------------------------
extern "C" void kernel_launch(void* const* d_in, const int* in_sizes, int n_in,
                              void* d_out, int out_size) {
    const float* A     = (const float*)d_in[0];   // (1024, 2048)
    const float* x     = (const float*)d_in[1];   // (1024, 64)
    const float* W     = (const float*)d_in[2];   // (64, 768)
    const float* bias  = (const float*)d_in[3];   // (64)
    const float* gamma = (const float*)d_in[4];   // (64)
    const float* beta  = (const float*)d_in[5];   // (64)
    const int*   b_n   = (const int*)d_in[6];     // (2048)
    float* out = (float*)d_out;                   // (2048, 64)

    cudaFuncSetAttribute(k4_gemm_ln, cudaFuncAttributeMaxDynamicSharedMemorySize, K4_SMEM);

    k_prep<<<448, 256>>>(W, A);
    k2_stats<<<NN / 4, 256>>>(x, b_n);
    k4_gemm_ln<<<NN / NPB, 256, K4_SMEM>>>(bias, gamma, beta, b_n, out);
}